// round 13
// baseline (speedup 1.0000x reference)
#include <cuda_runtime.h>
#include <math.h>

#define D    2048
#define E    64
#define NT   16384      // B*S tokens
#define KC   32         // k-chunk
#define TTOK 128        // tokens per gemm block
#define SB   128        // tokens per router block
#define NSB  (NT / SB)  // 128 router blocks

typedef unsigned long long ull;

// ---------------- device scratch (no allocations allowed) ----------------
__device__ float g_logits[(size_t)NT * E];   // 4 MB
__device__ float g_P[NSB * E];
__device__ float g_C[NSB * E];
__device__ float g_Z[NSB];

// ---------------- f32x2 helpers ------------------------------------------
__device__ __forceinline__ ull pack2(float lo, float hi) {
    ull r;
    asm("mov.b64 %0, {%1, %2};" : "=l"(r) : "r"(__float_as_uint(lo)), "r"(__float_as_uint(hi)));
    return r;
}
__device__ __forceinline__ void unpack2(ull v, float& lo, float& hi) {
    unsigned int a, b;
    asm("mov.b64 {%0, %1}, %2;" : "=r"(a), "=r"(b) : "l"(v));
    lo = __uint_as_float(a); hi = __uint_as_float(b);
}
__device__ __forceinline__ void fma2(ull& d, ull a, ull b) {
    asm("fma.rn.f32x2 %0, %1, %2, %0;" : "+l"(d) : "l"(a), "l"(b));
}

// ---------------- GEMM: logits[t][e] = sum_d x[t][d] * gw[e][d] ----------
// Block: 128 tokens x 64 experts, 256 threads. Thread: 4 tokens x 8 experts.
// f32x2 packed over the expert dimension; software-pipelined gmem loads.
__global__ void __launch_bounds__(256) gemm_kernel(const float* __restrict__ x,
                                                   const float* __restrict__ gw) {
    __shared__ float xs[KC][TTOK + 4];   // [k][token], row 132 floats (16B-mult)
    __shared__ float ws[KC][E + 4];      // [k][expert], row 68 floats (16B-mult)

    const int tid = threadIdx.x;
    const int t0  = blockIdx.x * TTOK;
    const int tg  = tid >> 3;            // 0..31 -> tokens tg*4 .. tg*4+3
    const int tx  = tid & 7;             // 0..7  -> experts tx*8 .. tx*8+7

    // x loader: row xr (0..127), k-half xh (0 or 16); 4 x LDG.128 per chunk
    const int xr = tid >> 1;
    const int xh = (tid & 1) * 16;
    // w loader: row wr (0..63), k-quarter wq; 2 x LDG.128 per chunk
    const int wr = tid >> 2;
    const int wq = (tid & 3) * 8;

    const float* xp = x  + (size_t)(t0 + xr) * D + xh;
    const float* wp = gw + (size_t)wr        * D + wq;

    ull acc[4][4];
#pragma unroll
    for (int i = 0; i < 4; i++)
#pragma unroll
        for (int j = 0; j < 4; j++) acc[i][j] = 0ULL;   // (0.f,0.f)

    // prefetch chunk 0
    float4 xa[4], wa[2];
#pragma unroll
    for (int j = 0; j < 4; j++) xa[j] = *(const float4*)(xp + j * 4);
#pragma unroll
    for (int j = 0; j < 2; j++) wa[j] = *(const float4*)(wp + j * 4);

    for (int kc = 0; kc < D; kc += KC) {
        __syncthreads();   // readers of previous chunk done
        // store current chunk (transposed) to smem
#pragma unroll
        for (int j = 0; j < 4; j++) {
            xs[xh + j * 4 + 0][xr] = xa[j].x;
            xs[xh + j * 4 + 1][xr] = xa[j].y;
            xs[xh + j * 4 + 2][xr] = xa[j].z;
            xs[xh + j * 4 + 3][xr] = xa[j].w;
        }
#pragma unroll
        for (int j = 0; j < 2; j++) {
            ws[wq + j * 4 + 0][wr] = wa[j].x;
            ws[wq + j * 4 + 1][wr] = wa[j].y;
            ws[wq + j * 4 + 2][wr] = wa[j].z;
            ws[wq + j * 4 + 3][wr] = wa[j].w;
        }
        __syncthreads();
        // prefetch next chunk (overlaps with compute below)
        if (kc + KC < D) {
#pragma unroll
            for (int j = 0; j < 4; j++) xa[j] = *(const float4*)(xp + kc + KC + j * 4);
#pragma unroll
            for (int j = 0; j < 2; j++) wa[j] = *(const float4*)(wp + kc + KC + j * 4);
        }
        // compute
#pragma unroll
        for (int kk = 0; kk < KC; kk++) {
            float4 av = *(const float4*)&xs[kk][tg * 4];
            float4 b0 = *(const float4*)&ws[kk][tx * 8];
            float4 b1 = *(const float4*)&ws[kk][tx * 8 + 4];
            ull B0 = pack2(b0.x, b0.y);
            ull B1 = pack2(b0.z, b0.w);
            ull B2 = pack2(b1.x, b1.y);
            ull B3 = pack2(b1.z, b1.w);
            ull A0 = pack2(av.x, av.x);
            ull A1 = pack2(av.y, av.y);
            ull A2 = pack2(av.z, av.z);
            ull A3 = pack2(av.w, av.w);
            fma2(acc[0][0], A0, B0); fma2(acc[0][1], A0, B1);
            fma2(acc[0][2], A0, B2); fma2(acc[0][3], A0, B3);
            fma2(acc[1][0], A1, B0); fma2(acc[1][1], A1, B1);
            fma2(acc[1][2], A1, B2); fma2(acc[1][3], A1, B3);
            fma2(acc[2][0], A2, B0); fma2(acc[2][1], A2, B1);
            fma2(acc[2][2], A2, B2); fma2(acc[2][3], A2, B3);
            fma2(acc[3][0], A3, B0); fma2(acc[3][1], A3, B1);
            fma2(acc[3][2], A3, B2); fma2(acc[3][3], A3, B3);
        }
    }

    // epilogue: tokens t0 + tg*4 + t, experts tx*8 .. tx*8+7
#pragma unroll
    for (int t = 0; t < 4; t++) {
        float r[8];
#pragma unroll
        for (int p = 0; p < 4; p++) unpack2(acc[t][p], r[2 * p], r[2 * p + 1]);
        float* dst = &g_logits[(size_t)(t0 + tg * 4 + t) * E + tx * 8];
        *(float4*)(dst)     = make_float4(r[0], r[1], r[2], r[3]);
        *(float4*)(dst + 4) = make_float4(r[4], r[5], r[6], r[7]);
    }
}

// ---------------- Router: softmax + top2 + partial aux -------------------
__global__ void __launch_bounds__(256) router_kernel(float* __restrict__ out) {
    __shared__ float sP[8][64];
    __shared__ int   sC[8][64];
    __shared__ float sZ[8];

    const int tid  = threadIdx.x;
    const int w    = tid >> 5;
    const int lane = tid & 31;

    sC[w][lane] = 0; sC[w][lane + 32] = 0;
    if (lane == 0) sZ[w] = 0.f;
    __syncwarp();

    float p0 = 0.f, p1 = 0.f, zacc = 0.f;
    const int tokBase = blockIdx.x * SB + w * 16;

    for (int it = 0; it < 16; it++) {
        const int tok = tokBase + it;
        const float* lrow = &g_logits[(size_t)tok * E];
        float l0 = lrow[lane];
        float l1 = lrow[lane + 32];

        float m = fmaxf(l0, l1);
#pragma unroll
        for (int o = 16; o > 0; o >>= 1) m = fmaxf(m, __shfl_xor_sync(0xffffffffu, m, o));

        float e0 = expf(l0 - m), e1 = expf(l1 - m);
        float s = e0 + e1;
#pragma unroll
        for (int o = 16; o > 0; o >>= 1) s += __shfl_xor_sync(0xffffffffu, s, o);

        float inv = 1.f / s;
        p0 += e0 * inv;
        p1 += e1 * inv;

        float lse = logf(s) + m;
        zacc += lse * lse;

        // top-1 candidate per lane (tie -> lower index, matching jax top_k)
        float bv; int bi;
        if (e1 > e0) { bv = e1; bi = lane + 32; } else { bv = e0; bi = lane; }
#pragma unroll
        for (int o = 16; o > 0; o >>= 1) {
            float ov = __shfl_xor_sync(0xffffffffu, bv, o);
            int   oi = __shfl_xor_sync(0xffffffffu, bi, o);
            if (ov > bv || (ov == bv && oi < bi)) { bv = ov; bi = oi; }
        }
        // top-2: exclude bi
        float b2; int b2i;
        if (bi == lane)            { b2 = e1; b2i = lane + 32; }
        else if (bi == lane + 32)  { b2 = e0; b2i = lane; }
        else if (e1 > e0)          { b2 = e1; b2i = lane + 32; }
        else                       { b2 = e0; b2i = lane; }
#pragma unroll
        for (int o = 16; o > 0; o >>= 1) {
            float ov = __shfl_xor_sync(0xffffffffu, b2, o);
            int   oi = __shfl_xor_sync(0xffffffffu, b2i, o);
            if (ov > b2 || (ov == b2 && oi < b2i)) { b2 = ov; b2i = oi; }
        }

        if (lane == 0) {
            float sw = bv + b2;
            out[tok * 2 + 0]           = (float)bi;
            out[tok * 2 + 1]           = (float)b2i;
            out[2 * NT + tok * 2 + 0]  = bv / sw;
            out[2 * NT + tok * 2 + 1]  = b2 / sw;
            sC[w][bi]++;
            sC[w][b2i]++;
        }
    }

    sP[w][lane] = p0;
    sP[w][lane + 32] = p1;
    if (lane == 0) sZ[w] = zacc;
    __syncthreads();

    if (tid < 64) {
        float ps = 0.f, cs = 0.f;
#pragma unroll
        for (int ww = 0; ww < 8; ww++) {
            ps += sP[ww][tid];
            cs += (float)sC[ww][tid];
        }
        g_P[blockIdx.x * E + tid] = ps;
        g_C[blockIdx.x * E + tid] = cs;
    }
    if (tid == 64) {
        float z = 0.f;
#pragma unroll
        for (int ww = 0; ww < 8; ww++) z += sZ[ww];
        g_Z[blockIdx.x] = z;
    }
}

// ---------------- Finalize aux loss --------------------------------------
__global__ void __launch_bounds__(64) finalize_kernel(float* __restrict__ out) {
    __shared__ float red[64];
    const int tid = threadIdx.x;   // 64 threads, one per expert
    float P = 0.f, C = 0.f;
    for (int b = 0; b < NSB; b++) {
        P += g_P[b * E + tid];
        C += g_C[b * E + tid];
    }
    float f  = C / (float)(NT * 2);
    float Pm = P / (float)NT;
    red[tid] = f * Pm;
    __syncthreads();
    for (int o = 32; o > 0; o >>= 1) {
        if (tid < o) red[tid] += red[tid + o];
        __syncthreads();
    }
    if (tid == 0) {
        float z = 0.f;
        for (int b = 0; b < NSB; b++) z += g_Z[b];
        float balance = (float)E * red[0];
        float zmean   = z / (float)NT;
        out[4 * NT] = 0.01f * balance + 0.001f * zmean;
    }
}

// ---------------- launch --------------------------------------------------
extern "C" void kernel_launch(void* const* d_in, const int* in_sizes, int n_in,
                              void* d_out, int out_size) {
    const float* x  = (const float*)d_in[0];
    const float* gw = (const float*)d_in[1];
    float* out = (float*)d_out;

    gemm_kernel<<<NT / TTOK, 256>>>(x, gw);
    router_kernel<<<NT / SB, 256>>>(out);
    finalize_kernel<<<1, 64>>>(out);
}